// round 2
// baseline (speedup 1.0000x reference)
#include <cuda_runtime.h>
#include <cuda_bf16.h>
#include <cstdint>
#include <cstddef>

#define DIM 768
#define MAXN 30000

// ---------------- static scratch (no allocations allowed) ----------------
__device__ float g_agg[MAXN * DIM];
__device__ float g_h  [MAXN * DIM];
__device__ float g_e  [MAXN * DIM];
__device__ float g_cnt[MAXN];
__device__ float g_rsc[MAXN];
__device__ float g_cs1[DIM];    // column sums of e1
__device__ float g_cst[DIM];    // column sums of et
__device__ float g_emb2[DIM];   // e1[var_idx]
__device__ float g_outv[DIM];   // final out vector

static inline int cdiv(int a, int b) { return (a + b - 1) / b; }

// ---------------- elementwise helpers ----------------
__global__ void zero_kernel(float* p, int n4) {  // zeroes n4 float4s
    int i = blockIdx.x * blockDim.x + threadIdx.x;
    if (i < n4) ((float4*)p)[i] = make_float4(0.f, 0.f, 0.f, 0.f);
}

__global__ void count_deg(float* cnt, const int* __restrict__ dst, int E) {
    int i = blockIdx.x * blockDim.x + threadIdx.x;
    if (i < E) atomicAdd(&cnt[dst[i]], 1.0f);
}

__global__ void make_rscale(float* rsc, const float* cnt, int N) {
    int i = blockIdx.x * blockDim.x + threadIdx.x;
    if (i < N) rsc[i] = 1.0f / fmaxf(cnt[i], 1.0f);
}

// scatter-add: agg[dst[e]] += x[src[e]]   (float4 granularity, 192 chunks/row)
__global__ void scatter_add(float* __restrict__ agg, const float* __restrict__ x,
                            const int* __restrict__ src, const int* __restrict__ dst,
                            long total) {
    long idx = (long)blockIdx.x * blockDim.x + threadIdx.x;
    if (idx >= total) return;
    int e = (int)(idx / 192);
    int c = (int)(idx % 192) * 4;
    int s = src[e], d = dst[e];
    float4 v = *(const float4*)(x + (size_t)s * DIM + c);
    float* o = agg + (size_t)d * DIM + c;
    atomicAdd(o + 0, v.x);
    atomicAdd(o + 1, v.y);
    atomicAdd(o + 2, v.z);
    atomicAdd(o + 3, v.w);
}

// ---------------- fused SAGE GEMM ----------------
// C[M,768] = (A0 * rscale_row) @ W0^T + A1 @ W1^T + bias, optional relu.
// W row-major [768,768]; both operands K-contiguous (TN-style).
// 128x128 tile, BK=16, 256 threads, 8x8 microtile with split-64 fragments.
__global__ __launch_bounds__(256)
void gemm_fused(const float* __restrict__ A0, const float* __restrict__ rsc,
                const float* __restrict__ W0,
                const float* __restrict__ A1, const float* __restrict__ W1,
                const float* __restrict__ bias, float* __restrict__ C,
                int M, int relu) {
    __shared__ __align__(16) float As[16][132];
    __shared__ __align__(16) float Bs[16][132];

    const int tid = threadIdx.x;
    const int tx = tid & 15;
    const int ty = tid >> 4;
    const int block_row = blockIdx.y * 128;
    const int block_col = blockIdx.x * 128;

    float acc[8][8];
#pragma unroll
    for (int i = 0; i < 8; i++)
#pragma unroll
        for (int j = 0; j < 8; j++) acc[i][j] = 0.f;

#pragma unroll 1
    for (int pair = 0; pair < 2; ++pair) {
        const float* A = pair ? A1 : A0;
        const float* W = pair ? W1 : W0;
        const bool doScale = (pair == 0);

#pragma unroll 1
        for (int k0 = 0; k0 < DIM; k0 += 16) {
            // load A tile (128 rows x 16 k), 512 float4 by 256 threads
#pragma unroll
            for (int l = 0; l < 2; ++l) {
                int idx = tid + l * 256;
                int r = idx >> 2;
                int kq = idx & 3;
                int grow = block_row + r;
                float4 v = make_float4(0.f, 0.f, 0.f, 0.f);
                if (grow < M) {
                    v = *(const float4*)(A + (size_t)grow * DIM + k0 + kq * 4);
                    if (doScale) {
                        float s = rsc[grow];
                        v.x *= s; v.y *= s; v.z *= s; v.w *= s;
                    }
                }
                As[kq * 4 + 0][r] = v.x;
                As[kq * 4 + 1][r] = v.y;
                As[kq * 4 + 2][r] = v.z;
                As[kq * 4 + 3][r] = v.w;
            }
            // load W tile: 128 output-cols (rows of W) x 16 k
#pragma unroll
            for (int l = 0; l < 2; ++l) {
                int idx = tid + l * 256;
                int r = idx >> 2;
                int kq = idx & 3;
                int gcol = block_col + r;  // < 768 always
                float4 v = *(const float4*)(W + (size_t)gcol * DIM + k0 + kq * 4);
                Bs[kq * 4 + 0][r] = v.x;
                Bs[kq * 4 + 1][r] = v.y;
                Bs[kq * 4 + 2][r] = v.z;
                Bs[kq * 4 + 3][r] = v.w;
            }
            __syncthreads();

#pragma unroll
            for (int k = 0; k < 16; ++k) {
                float a[8], b[8];
                *(float4*)&a[0] = *(const float4*)&As[k][ty * 4];
                *(float4*)&a[4] = *(const float4*)&As[k][64 + ty * 4];
                *(float4*)&b[0] = *(const float4*)&Bs[k][tx * 4];
                *(float4*)&b[4] = *(const float4*)&Bs[k][64 + tx * 4];
#pragma unroll
                for (int i = 0; i < 8; i++)
#pragma unroll
                    for (int j = 0; j < 8; j++) acc[i][j] += a[i] * b[j];
            }
            __syncthreads();
        }
    }

    // epilogue: bias + optional relu
#pragma unroll
    for (int i = 0; i < 8; i++) {
        int grow = block_row + (i >> 2) * 64 + ty * 4 + (i & 3);
        if (grow >= M) continue;
#pragma unroll
        for (int jj = 0; jj < 2; jj++) {
            int col = block_col + jj * 64 + tx * 4;
            float4 c;
            c.x = acc[i][jj * 4 + 0] + bias[col + 0];
            c.y = acc[i][jj * 4 + 1] + bias[col + 1];
            c.z = acc[i][jj * 4 + 2] + bias[col + 2];
            c.w = acc[i][jj * 4 + 3] + bias[col + 3];
            if (relu) {
                c.x = fmaxf(c.x, 0.f); c.y = fmaxf(c.y, 0.f);
                c.z = fmaxf(c.z, 0.f); c.w = fmaxf(c.w, 0.f);
            }
            *(float4*)(C + (size_t)grow * DIM + col) = c;
        }
    }
}

// ---------------- reductions / tail ----------------
__global__ void colsum_kernel(const float* __restrict__ e, float* __restrict__ cs, int M) {
    int r0 = blockIdx.x * 128;
    int rEnd = min(r0 + 128, M);
    float local0 = 0.f, local1 = 0.f, local2 = 0.f;
    for (int r = r0; r < rEnd; ++r) {
        const float* row = e + (size_t)r * DIM;
        local0 += row[threadIdx.x];
        local1 += row[threadIdx.x + 256];
        local2 += row[threadIdx.x + 512];
    }
    atomicAdd(&cs[threadIdx.x], local0);
    atomicAdd(&cs[threadIdx.x + 256], local1);
    atomicAdd(&cs[threadIdx.x + 512], local2);
}

__global__ void copy_row(const float* __restrict__ e, const int* __restrict__ varIdx,
                         float* __restrict__ dstv) {
    int i = blockIdx.x * blockDim.x + threadIdx.x;
    if (i < DIM) dstv[i] = e[(size_t)(*varIdx) * DIM + i];
}

// out[i] = (linW[i,:] . feats + linb[i]) * Wo[op-1, i];  feats = [emb1, emb2, emb1*emb2]
__global__ void lin_out(const float* __restrict__ cs1, float n1inv,
                        const float* __restrict__ emb2,
                        const float* __restrict__ linW, const float* __restrict__ linb,
                        const float* __restrict__ Wo, const int* __restrict__ opPtr,
                        float* __restrict__ d_out, float* __restrict__ outv) {
    int i = blockIdx.x;
    const float* wrow = linW + (size_t)i * (3 * DIM);
    float sum = 0.f;
    for (int j = threadIdx.x; j < 3 * DIM; j += 256) {
        float f;
        if (j < DIM) f = cs1[j] * n1inv;
        else if (j < 2 * DIM) f = emb2[j - DIM];
        else f = cs1[j - 2 * DIM] * n1inv * emb2[j - 2 * DIM];
        sum += wrow[j] * f;
    }
    __shared__ float sh[256];
    sh[threadIdx.x] = sum;
    __syncthreads();
    for (int s = 128; s > 0; s >>= 1) {
        if (threadIdx.x < s) sh[threadIdx.x] += sh[threadIdx.x + s];
        __syncthreads();
    }
    if (threadIdx.x == 0) {
        int op = *opPtr;
        float o = (sh[0] + linb[i]) * Wo[(size_t)(op - 1) * DIM + i];
        d_out[3 + i] = o;
        outv[i] = o;
    }
}

__global__ void finalize(const float* __restrict__ outv, const float* __restrict__ cst,
                         float ntinv, const float* __restrict__ ov,
                         const int* __restrict__ opPtr, const float* __restrict__ labels,
                         float* __restrict__ d_out) {
    int op = *opPtr;
    float s_dot = 0.f, s_no = 0.f, s_nt = 0.f;
    for (int i = threadIdx.x; i < DIM; i += 256) {
        float o = outv[i];
        float t = cst[i] * ntinv + ov[(size_t)(op - 1) * DIM + i];
        s_dot += o * t;
        s_no += o * o;
        s_nt += t * t;
    }
    __shared__ float shd[256], sho[256], sht[256];
    shd[threadIdx.x] = s_dot; sho[threadIdx.x] = s_no; sht[threadIdx.x] = s_nt;
    __syncthreads();
    for (int s = 128; s > 0; s >>= 1) {
        if (threadIdx.x < s) {
            shd[threadIdx.x] += shd[threadIdx.x + s];
            sho[threadIdx.x] += sho[threadIdx.x + s];
            sht[threadIdx.x] += sht[threadIdx.x + s];
        }
        __syncthreads();
    }
    if (threadIdx.x == 0) {
        const float eps = 1e-8f;
        float no = fmaxf(sqrtf(sho[0]), eps);
        float nt = fmaxf(sqrtf(sht[0]), eps);
        float score = shd[0] / (no * nt);
        float lab = labels[0];
        float diff = score - lab;
        d_out[0] = diff * diff;
        d_out[1] = score;
        d_out[2] = lab;
    }
}

// ---------------- host orchestration ----------------
struct Scratch {
    float *agg, *h, *e, *cnt, *rsc, *cs1, *cst, *emb2, *outv;
};

static const Scratch& get_scratch() {
    static Scratch s = [] {
        Scratch t;
        cudaGetSymbolAddress((void**)&t.agg,  g_agg);
        cudaGetSymbolAddress((void**)&t.h,    g_h);
        cudaGetSymbolAddress((void**)&t.e,    g_e);
        cudaGetSymbolAddress((void**)&t.cnt,  g_cnt);
        cudaGetSymbolAddress((void**)&t.rsc,  g_rsc);
        cudaGetSymbolAddress((void**)&t.cs1,  g_cs1);
        cudaGetSymbolAddress((void**)&t.cst,  g_cst);
        cudaGetSymbolAddress((void**)&t.emb2, g_emb2);
        cudaGetSymbolAddress((void**)&t.outv, g_outv);
        return t;
    }();
    return s;
}

static void encode_graph(const float* x, const int* ei, int N, int E,
                         const float* Wl1, const float* bl1, const float* Wr1,
                         const float* Wl2, const float* bl2, const float* Wr2,
                         float* agg, float* h, float* e, float* cnt, float* rsc) {
    const int* src = ei;
    const int* dst = ei + E;
    long total = (long)E * 192;
    int sBlocks = (int)((total + 255) / 256);
    dim3 gGrid(DIM / 128, cdiv(N, 128));

    zero_kernel<<<cdiv(cdiv(N, 4), 256), 256>>>(cnt, cdiv(N, 4));
    count_deg<<<cdiv(E, 256), 256>>>(cnt, dst, E);
    make_rscale<<<cdiv(N, 256), 256>>>(rsc, cnt, N);

    // layer 1
    zero_kernel<<<cdiv(N * (DIM / 4), 256), 256>>>(agg, N * (DIM / 4));
    scatter_add<<<sBlocks, 256>>>(agg, x, src, dst, total);
    gemm_fused<<<gGrid, 256>>>(agg, rsc, Wl1, x, Wr1, bl1, h, N, 1);

    // layer 2
    zero_kernel<<<cdiv(N * (DIM / 4), 256), 256>>>(agg, N * (DIM / 4));
    scatter_add<<<sBlocks, 256>>>(agg, h, src, dst, total);
    gemm_fused<<<gGrid, 256>>>(agg, rsc, Wl2, h, Wr2, bl2, e, N, 0);
}

extern "C" void kernel_launch(void* const* d_in, const int* in_sizes, int n_in,
                              void* d_out, int out_size) {
    const float* x1   = (const float*)d_in[0];
    const int*   ei1  = (const int*)d_in[1];
    const int*   vidx = (const int*)d_in[2];
    const float* xt   = (const float*)d_in[3];
    const int*   eit  = (const int*)d_in[4];
    const int*   op   = (const int*)d_in[5];
    const float* lab  = (const float*)d_in[6];
    const float* Wl1  = (const float*)d_in[7];
    const float* bl1  = (const float*)d_in[8];
    const float* Wr1  = (const float*)d_in[9];
    const float* Wl2  = (const float*)d_in[10];
    const float* bl2  = (const float*)d_in[11];
    const float* Wr2  = (const float*)d_in[12];
    const float* linW = (const float*)d_in[13];
    const float* linb = (const float*)d_in[14];
    const float* Wo   = (const float*)d_in[15];
    const float* ov   = (const float*)d_in[16];
    float* out = (float*)d_out;

    int N1 = in_sizes[0] / DIM;
    int E1 = in_sizes[1] / 2;
    int NT = in_sizes[3] / DIM;
    int ET = in_sizes[4] / 2;

    const Scratch& S = get_scratch();

    // ----- graph 1 -----
    encode_graph(x1, ei1, N1, E1, Wl1, bl1, Wr1, Wl2, bl2, Wr2,
                 S.agg, S.h, S.e, S.cnt, S.rsc);
    zero_kernel<<<1, DIM / 4>>>(S.cs1, DIM / 4);
    colsum_kernel<<<cdiv(N1, 128), 256>>>(S.e, S.cs1, N1);
    copy_row<<<3, 256>>>(S.e, vidx, S.emb2);

    // ----- graph t (reuses scratch) -----
    encode_graph(xt, eit, NT, ET, Wl1, bl1, Wr1, Wl2, bl2, Wr2,
                 S.agg, S.h, S.e, S.cnt, S.rsc);
    zero_kernel<<<1, DIM / 4>>>(S.cst, DIM / 4);
    colsum_kernel<<<cdiv(NT, 128), 256>>>(S.e, S.cst, NT);

    // ----- tail -----
    lin_out<<<DIM, 256>>>(S.cs1, 1.0f / (float)N1, S.emb2, linW, linb, Wo, op, out, S.outv);
    finalize<<<1, 256>>>(S.outv, S.cst, 1.0f / (float)NT, ov, op, lab, out);
}

// round 5
// speedup vs baseline: 1.5674x; 1.5674x over previous
#include <cuda_runtime.h>
#include <cstdint>
#include <cstddef>

#define DIM 768
#define MAXN 30000

// GEMM tile config
#define BM 128
#define BN 128
#define BK 32
#define LDA 36                      // row stride in floats (BK + 4 pad, 16B aligned)
#define TILE_F (BM * LDA)           // 4608 floats per operand tile
#define STAGE_F (2 * TILE_F)        // A + B per stage
#define SMEM_GEMM_BYTES (2 * STAGE_F * 4)   // 73728
#define KT_PER_MAT 24               // 768/32
#define KT_TOTAL 48                 // fused K = 2*768

// ---------------- static scratch ----------------
__device__ float g_agg[MAXN * DIM];
__device__ float g_h  [MAXN * DIM];
__device__ float g_e  [MAXN * DIM];
__device__ float g_cnt[MAXN];
__device__ float g_rsc[MAXN];
__device__ float g_cs1[DIM];
__device__ float g_cst[DIM];
__device__ float g_emb2[DIM];
__device__ float g_outv[DIM];

static inline int cdiv(int a, int b) { return (a + b - 1) / b; }

// ---------------- PTX helpers ----------------
__device__ __forceinline__ uint32_t smem_u32(const void* p) {
    uint32_t a;
    asm("{ .reg .u64 t; cvta.to.shared.u64 t, %1; cvt.u32.u64 %0, t; }" : "=r"(a) : "l"(p));
    return a;
}

__device__ __forceinline__ void cp16(uint32_t dst, const void* src, bool valid) {
    int sz = valid ? 16 : 0;
    asm volatile("cp.async.cg.shared.global [%0], [%1], 16, %2;\n"
                 :: "r"(dst), "l"(src), "r"(sz) : "memory");
}
#define CP_COMMIT() asm volatile("cp.async.commit_group;\n" ::: "memory")
template <int N>
__device__ __forceinline__ void cp_wait() {
    asm volatile("cp.async.wait_group %0;\n" :: "n"(N) : "memory");
}

__device__ __forceinline__ uint32_t f2tf32(float x) {
    uint32_t r;
    asm("cvt.rna.tf32.f32 %0, %1;" : "=r"(r) : "f"(x));
    return r;
}

__device__ __forceinline__ void mma_tf32(float* c, const uint32_t* a, const uint32_t* b) {
    asm volatile(
        "mma.sync.aligned.m16n8k8.row.col.f32.tf32.tf32.f32 "
        "{%0,%1,%2,%3}, {%4,%5,%6,%7}, {%8,%9}, {%0,%1,%2,%3};"
        : "+f"(c[0]), "+f"(c[1]), "+f"(c[2]), "+f"(c[3])
        : "r"(a[0]), "r"(a[1]), "r"(a[2]), "r"(a[3]), "r"(b[0]), "r"(b[1]));
}

// ---------------- small kernels ----------------
__global__ void count_deg(float* cnt, const int* __restrict__ dst, int E) {
    int i = blockIdx.x * blockDim.x + threadIdx.x;
    if (i < E) atomicAdd(&cnt[dst[i]], 1.0f);
}

__global__ void make_rscale(float* rsc, const float* cnt, int N) {
    int i = blockIdx.x * blockDim.x + threadIdx.x;
    if (i < N) rsc[i] = 1.0f / fmaxf(cnt[i], 1.0f);
}

// scatter-mean contribution: agg[dst[e]] += x[src[e]] * rsc[dst[e]]
__global__ void scatter_add(float* __restrict__ agg, const float* __restrict__ x,
                            const int* __restrict__ src, const int* __restrict__ dst,
                            const float* __restrict__ rsc, long total) {
    long idx = (long)blockIdx.x * blockDim.x + threadIdx.x;
    if (idx >= total) return;
    int e = (int)(idx / 192);
    int c = (int)(idx % 192) * 4;
    int s = src[e], d = dst[e];
    float r = rsc[d];
    float4 v = *(const float4*)(x + (size_t)s * DIM + c);
    float* o = agg + (size_t)d * DIM + c;
    atomicAdd(o + 0, v.x * r);
    atomicAdd(o + 1, v.y * r);
    atomicAdd(o + 2, v.z * r);
    atomicAdd(o + 3, v.w * r);
}

// ---------------- mma.sync tf32 fused SAGE GEMM ----------------
// C[M,768] = A0 @ W0^T + A1 @ W1^T + bias  (optional relu). Row-major, K-contiguous.
__global__ __launch_bounds__(256)
void gemm_mma(const float* __restrict__ A0, const float* __restrict__ A1,
              const float* __restrict__ W0, const float* __restrict__ W1,
              const float* __restrict__ bias, float* __restrict__ C,
              int M, int relu) {
    extern __shared__ __align__(16) float sm[];
    const int tid = threadIdx.x;
    const int w = tid >> 5;
    const int lane = tid & 31;
    const int g = lane >> 2;       // groupID
    const int t = lane & 3;        // threadID_in_group
    const int wr = w >> 2;         // 0..1
    const int wc = w & 3;          // 0..3
    const int wm0 = wr * 64;
    const int wn0 = wc * 32;
    const int row0 = blockIdx.y * BM;
    const int col0 = blockIdx.x * BN;

    float acc[4][4][4];
#pragma unroll
    for (int mt = 0; mt < 4; mt++)
#pragma unroll
        for (int nt = 0; nt < 4; nt++)
#pragma unroll
            for (int i = 0; i < 4; i++) acc[mt][nt][i] = 0.f;

    // precomputed per-thread chunk coords for tile loads (4 16B chunks/operand)
    int lm[4], lkq[4];
#pragma unroll
    for (int i = 0; i < 4; i++) {
        int c = tid + i * 256;
        lm[i] = c >> 3;
        lkq[i] = (c & 7) * 4;
    }

#define LOAD_TILE(kt_) do {                                                        \
    int _kt = (kt_);                                                               \
    int _pair = _kt >= KT_PER_MAT;                                                 \
    int _kk0 = (_kt - (_pair ? KT_PER_MAT : 0)) * BK;                              \
    const float* _A = _pair ? A1 : A0;                                             \
    const float* _W = _pair ? W1 : W0;                                             \
    float* _As = sm + (_kt & 1) * STAGE_F;                                         \
    float* _Bs = _As + TILE_F;                                                     \
    _Pragma("unroll")                                                              \
    for (int _i = 0; _i < 4; _i++) {                                               \
        int _m = lm[_i], _kq = lkq[_i];                                            \
        cp16(smem_u32(_As + _m * LDA + _kq),                                       \
             _A + (size_t)(row0 + _m) * DIM + _kk0 + _kq, (row0 + _m) < M);        \
        cp16(smem_u32(_Bs + _m * LDA + _kq),                                       \
             _W + (size_t)(col0 + _m) * DIM + _kk0 + _kq, true);                   \
    }                                                                              \
    CP_COMMIT();                                                                   \
} while (0)

    LOAD_TILE(0);

#pragma unroll 1
    for (int kt = 0; kt < KT_TOTAL; kt++) {
        if (kt + 1 < KT_TOTAL) {
            LOAD_TILE(kt + 1);
            cp_wait<1>();
        } else {
            cp_wait<0>();
        }
        __syncthreads();

        float* As = sm + (kt & 1) * STAGE_F;
        // in-place fp32 -> tf32(rna) conversion over both operand tiles (incl. pad)
#pragma unroll
        for (int i = 0; i < 9; i++) {
            float4* p = (float4*)As + tid + i * 256;   // 2304 float4 total
            float4 v = *p;
            uint4 u;
            u.x = f2tf32(v.x); u.y = f2tf32(v.y);
            u.z = f2tf32(v.z); u.w = f2tf32(v.w);
            *(uint4*)p = u;
        }
        __syncthreads();

        const float* Af = As;
        const float* Bf = As + TILE_F;
#pragma unroll
        for (int kk = 0; kk < BK; kk += 8) {
            uint32_t a[4][4], b[4][2];
#pragma unroll
            for (int mt = 0; mt < 4; mt++) {
                const float* base = Af + (wm0 + mt * 16 + g) * LDA + kk + t;
                a[mt][0] = __float_as_uint(base[0]);
                a[mt][1] = __float_as_uint(base[8 * LDA]);
                a[mt][2] = __float_as_uint(base[4]);
                a[mt][3] = __float_as_uint(base[8 * LDA + 4]);
            }
#pragma unroll
            for (int nt = 0; nt < 4; nt++) {
                const float* base = Bf + (wn0 + nt * 8 + g) * LDA + kk + t;
                b[nt][0] = __float_as_uint(base[0]);
                b[nt][1] = __float_as_uint(base[4]);
            }
#pragma unroll
            for (int mt = 0; mt < 4; mt++)
#pragma unroll
                for (int nt = 0; nt < 4; nt++)
                    mma_tf32(acc[mt][nt], a[mt], b[nt]);
        }
        __syncthreads();
    }

    // epilogue: bias + optional relu
#pragma unroll
    for (int mt = 0; mt < 4; mt++) {
#pragma unroll
        for (int half = 0; half < 2; half++) {
            int r = row0 + wm0 + mt * 16 + g + half * 8;
            if (r >= M) continue;
#pragma unroll
            for (int nt = 0; nt < 4; nt++) {
                int cc = col0 + wn0 + nt * 8 + 2 * t;
                float2 v;
                v.x = acc[mt][nt][half * 2 + 0] + bias[cc + 0];
                v.y = acc[mt][nt][half * 2 + 1] + bias[cc + 1];
                if (relu) { v.x = fmaxf(v.x, 0.f); v.y = fmaxf(v.y, 0.f); }
                *(float2*)(C + (size_t)r * DIM + cc) = v;
            }
        }
    }
#undef LOAD_TILE
}

// ---------------- reductions / tail ----------------
__global__ void colsum_kernel(const float* __restrict__ e, float* __restrict__ cs, int M) {
    int r0 = blockIdx.x * 128;
    int rEnd = min(r0 + 128, M);
    float l0 = 0.f, l1 = 0.f, l2 = 0.f;
    for (int r = r0; r < rEnd; ++r) {
        const float* row = e + (size_t)r * DIM;
        l0 += row[threadIdx.x];
        l1 += row[threadIdx.x + 256];
        l2 += row[threadIdx.x + 512];
    }
    atomicAdd(&cs[threadIdx.x], l0);
    atomicAdd(&cs[threadIdx.x + 256], l1);
    atomicAdd(&cs[threadIdx.x + 512], l2);
}

__global__ void copy_row(const float* __restrict__ e, const int* __restrict__ varIdx,
                         float* __restrict__ dstv) {
    int i = blockIdx.x * blockDim.x + threadIdx.x;
    if (i < DIM) dstv[i] = e[(size_t)(*varIdx) * DIM + i];
}

__global__ void lin_out(const float* __restrict__ cs1, float n1inv,
                        const float* __restrict__ emb2,
                        const float* __restrict__ linW, const float* __restrict__ linb,
                        const float* __restrict__ Wo, const int* __restrict__ opPtr,
                        float* __restrict__ d_out, float* __restrict__ outv) {
    int i = blockIdx.x;
    const float* wrow = linW + (size_t)i * (3 * DIM);
    float sum = 0.f;
    for (int j = threadIdx.x; j < 3 * DIM; j += 256) {
        float f;
        if (j < DIM) f = cs1[j] * n1inv;
        else if (j < 2 * DIM) f = emb2[j - DIM];
        else f = cs1[j - 2 * DIM] * n1inv * emb2[j - 2 * DIM];
        sum += wrow[j] * f;
    }
    __shared__ float sh[256];
    sh[threadIdx.x] = sum;
    __syncthreads();
    for (int s = 128; s > 0; s >>= 1) {
        if (threadIdx.x < s) sh[threadIdx.x] += sh[threadIdx.x + s];
        __syncthreads();
    }
    if (threadIdx.x == 0) {
        int op = *opPtr;
        float o = (sh[0] + linb[i]) * Wo[(size_t)(op - 1) * DIM + i];
        d_out[3 + i] = o;
        outv[i] = o;
    }
}

__global__ void finalize(const float* __restrict__ outv, const float* __restrict__ cst,
                         float ntinv, const float* __restrict__ ov,
                         const int* __restrict__ opPtr, const float* __restrict__ labels,
                         float* __restrict__ d_out) {
    int op = *opPtr;
    float s_dot = 0.f, s_no = 0.f, s_nt = 0.f;
    for (int i = threadIdx.x; i < DIM; i += 256) {
        float o = outv[i];
        float t = cst[i] * ntinv + ov[(size_t)(op - 1) * DIM + i];
        s_dot += o * t; s_no += o * o; s_nt += t * t;
    }
    __shared__ float shd[256], sho[256], sht[256];
    shd[threadIdx.x] = s_dot; sho[threadIdx.x] = s_no; sht[threadIdx.x] = s_nt;
    __syncthreads();
    for (int s = 128; s > 0; s >>= 1) {
        if (threadIdx.x < s) {
            shd[threadIdx.x] += shd[threadIdx.x + s];
            sho[threadIdx.x] += sho[threadIdx.x + s];
            sht[threadIdx.x] += sht[threadIdx.x + s];
        }
        __syncthreads();
    }
    if (threadIdx.x == 0) {
        const float eps = 1e-8f;
        float no = fmaxf(sqrtf(sho[0]), eps);
        float nt = fmaxf(sqrtf(sht[0]), eps);
        float score = shd[0] / (no * nt);
        float lab = labels[0];
        float diff = score - lab;
        d_out[0] = diff * diff;
        d_out[1] = score;
        d_out[2] = lab;
    }
}

// ---------------- host orchestration ----------------
struct Scratch {
    float *agg, *h, *e, *cnt, *rsc, *cs1, *cst, *emb2, *outv;
};

static const Scratch& get_scratch() {
    static Scratch s = [] {
        Scratch t;
        cudaGetSymbolAddress((void**)&t.agg,  g_agg);
        cudaGetSymbolAddress((void**)&t.h,    g_h);
        cudaGetSymbolAddress((void**)&t.e,    g_e);
        cudaGetSymbolAddress((void**)&t.cnt,  g_cnt);
        cudaGetSymbolAddress((void**)&t.rsc,  g_rsc);
        cudaGetSymbolAddress((void**)&t.cs1,  g_cs1);
        cudaGetSymbolAddress((void**)&t.cst,  g_cst);
        cudaGetSymbolAddress((void**)&t.emb2, g_emb2);
        cudaGetSymbolAddress((void**)&t.outv, g_outv);
        cudaFuncSetAttribute(gemm_mma, cudaFuncAttributeMaxDynamicSharedMemorySize,
                             SMEM_GEMM_BYTES);
        return t;
    }();
    return s;
}

static void encode_graph(const float* x, const int* ei, int N, int E,
                         const float* Wl1, const float* bl1, const float* Wr1,
                         const float* Wl2, const float* bl2, const float* Wr2,
                         float* agg, float* h, float* e, float* cnt, float* rsc) {
    const int* src = ei;
    const int* dst = ei + E;
    long total = (long)E * 192;
    int sBlocks = (int)((total + 255) / 256);
    dim3 gGrid(DIM / BN, cdiv(N, BM));
    size_t aggBytes = (size_t)N * DIM * sizeof(float);

    cudaMemsetAsync(cnt, 0, (size_t)N * sizeof(float));
    count_deg<<<cdiv(E, 256), 256>>>(cnt, dst, E);
    make_rscale<<<cdiv(N, 256), 256>>>(rsc, cnt, N);

    // layer 1: h = relu(mean_agg(x) @ Wl1^T + bl1 + x @ Wr1^T)
    cudaMemsetAsync(agg, 0, aggBytes);
    scatter_add<<<sBlocks, 256>>>(agg, x, src, dst, rsc, total);
    gemm_mma<<<gGrid, 256, SMEM_GEMM_BYTES>>>(agg, x, Wl1, Wr1, bl1, h, N, 1);

    // layer 2: e = mean_agg(h) @ Wl2^T + bl2 + h @ Wr2^T
    cudaMemsetAsync(agg, 0, aggBytes);
    scatter_add<<<sBlocks, 256>>>(agg, h, src, dst, rsc, total);
    gemm_mma<<<gGrid, 256, SMEM_GEMM_BYTES>>>(agg, h, Wl2, Wr2, bl2, e, N, 0);
}

extern "C" void kernel_launch(void* const* d_in, const int* in_sizes, int n_in,
                              void* d_out, int out_size) {
    const float* x1   = (const float*)d_in[0];
    const int*   ei1  = (const int*)d_in[1];
    const int*   vidx = (const int*)d_in[2];
    const float* xt   = (const float*)d_in[3];
    const int*   eit  = (const int*)d_in[4];
    const int*   op   = (const int*)d_in[5];
    const float* lab  = (const float*)d_in[6];
    const float* Wl1  = (const float*)d_in[7];
    const float* bl1  = (const float*)d_in[8];
    const float* Wr1  = (const float*)d_in[9];
    const float* Wl2  = (const float*)d_in[10];
    const float* bl2  = (const float*)d_in[11];
    const float* Wr2  = (const float*)d_in[12];
    const float* linW = (const float*)d_in[13];
    const float* linb = (const float*)d_in[14];
    const float* Wo   = (const float*)d_in[15];
    const float* ov   = (const float*)d_in[16];
    float* out = (float*)d_out;

    int N1 = in_sizes[0] / DIM;
    int E1 = in_sizes[1] / 2;
    int NT = in_sizes[3] / DIM;
    int ET = in_sizes[4] / 2;

    const Scratch& S = get_scratch();

    // ----- graph 1 -----
    encode_graph(x1, ei1, N1, E1, Wl1, bl1, Wr1, Wl2, bl2, Wr2,
                 S.agg, S.h, S.e, S.cnt, S.rsc);
    cudaMemsetAsync(S.cs1, 0, DIM * sizeof(float));
    colsum_kernel<<<cdiv(N1, 128), 256>>>(S.e, S.cs1, N1);
    copy_row<<<3, 256>>>(S.e, vidx, S.emb2);

    // ----- graph t -----
    encode_graph(xt, eit, NT, ET, Wl1, bl1, Wr1, Wl2, bl2, Wr2,
                 S.agg, S.h, S.e, S.cnt, S.rsc);
    cudaMemsetAsync(S.cst, 0, DIM * sizeof(float));
    colsum_kernel<<<cdiv(NT, 128), 256>>>(S.e, S.cst, NT);

    // ----- tail -----
    lin_out<<<DIM, 256>>>(S.cs1, 1.0f / (float)N1, S.emb2, linW, linb, Wo, op, out, S.outv);
    finalize<<<1, 256>>>(S.outv, S.cst, 1.0f / (float)NT, ov, op, lab, out);
}